// round 1
// baseline (speedup 1.0000x reference)
#include <cuda_runtime.h>

// Fused 5-point replicate-pad stencil + cubic Horner polynomial.
// x: [P, H, W] fp32 planes (P = B*C), a: [3], w: [4].
// out[p,r,c] = a0*x + a1*(left+right) + a2*(up+down) + (((w3*x+w2)*x+w1)*x+w0)
// (CONST = 0 baked in: d == x)

#define H_DIM 2048
#define W_DIM 2048

__global__ void __launch_bounds__(256) stencil_poly_vec4(
    const float* __restrict__ x,
    const float* __restrict__ a,
    const float* __restrict__ w,
    float* __restrict__ out,
    int nplanes)
{
    const int W4 = W_DIM >> 2;
    long long tid = (long long)blockIdx.x * blockDim.x + threadIdx.x;
    long long total = (long long)nplanes * H_DIM * W4;
    if (tid >= total) return;

    int c4 = (int)(tid % W4);
    long long t2 = tid / W4;
    int r = (int)(t2 % H_DIM);
    int p = (int)(t2 / H_DIM);

    const float* plane = x + (long long)p * H_DIM * W_DIM;
    const float* rowp  = plane + (long long)r * W_DIM;

    // center vector
    float4 v = __ldg((const float4*)rowp + c4);

    // vertical neighbors with replicate clamp
    int rup = r > 0 ? r - 1 : 0;
    int rdn = r < H_DIM - 1 ? r + 1 : H_DIM - 1;
    float4 u = __ldg((const float4*)(plane + (long long)rup * W_DIM) + c4);
    float4 d = __ldg((const float4*)(plane + (long long)rdn * W_DIM) + c4);

    // horizontal halo with replicate clamp
    int c = c4 << 2;
    float left  = (c == 0)          ? v.x : __ldg(rowp + c - 1);
    float right = (c + 4 == W_DIM)  ? v.w : __ldg(rowp + c + 4);

    float a0 = __ldg(a + 0), a1 = __ldg(a + 1), a2 = __ldg(a + 2);
    float w0 = __ldg(w + 0), w1 = __ldg(w + 1), w2 = __ldg(w + 2), w3 = __ldg(w + 3);

    float4 o;
    {
        float xv = v.x;
        float st = a0 * xv + a1 * (left + v.y) + a2 * (u.x + d.x);
        float pl = fmaf(fmaf(fmaf(w3, xv, w2), xv, w1), xv, w0);
        o.x = st + pl;
    }
    {
        float xv = v.y;
        float st = a0 * xv + a1 * (v.x + v.z) + a2 * (u.y + d.y);
        float pl = fmaf(fmaf(fmaf(w3, xv, w2), xv, w1), xv, w0);
        o.y = st + pl;
    }
    {
        float xv = v.z;
        float st = a0 * xv + a1 * (v.y + v.w) + a2 * (u.z + d.z);
        float pl = fmaf(fmaf(fmaf(w3, xv, w2), xv, w1), xv, w0);
        o.z = st + pl;
    }
    {
        float xv = v.w;
        float st = a0 * xv + a1 * (v.z + right) + a2 * (u.w + d.w);
        float pl = fmaf(fmaf(fmaf(w3, xv, w2), xv, w1), xv, w0);
        o.w = st + pl;
    }

    float4* orow = (float4*)(out + (long long)p * H_DIM * W_DIM + (long long)r * W_DIM);
    orow[c4] = o;
}

extern "C" void kernel_launch(void* const* d_in, const int* in_sizes, int n_in,
                              void* d_out, int out_size)
{
    const float* x = (const float*)d_in[0];
    const float* a = (const float*)d_in[1];
    const float* w = (const float*)d_in[2];
    float* out = (float*)d_out;

    int n = in_sizes[0];
    int nplanes = n / (H_DIM * W_DIM);  // B*C = 16

    long long total4 = (long long)nplanes * H_DIM * (W_DIM / 4);
    int threads = 256;
    long long blocks = (total4 + threads - 1) / threads;

    stencil_poly_vec4<<<(unsigned)blocks, threads>>>(x, a, w, out, nplanes);
}

// round 2
// speedup vs baseline: 1.0034x; 1.0034x over previous
#include <cuda_runtime.h>

// Fused 5-point replicate-pad stencil + cubic Horner polynomial.
// R2: horizontal halo via warp shuffle instead of scalar LDGs (cuts L1
// wavefronts/thread from ~6 to ~4). Warps are row-aligned: W4=512, 512%32==0.

#define H_DIM 2048
#define W_DIM 2048

__global__ void __launch_bounds__(256) stencil_poly_vec4(
    const float* __restrict__ x,
    const float* __restrict__ a,
    const float* __restrict__ w,
    float* __restrict__ out,
    int nplanes)
{
    const int W4 = W_DIM >> 2;
    long long tid = (long long)blockIdx.x * blockDim.x + threadIdx.x;
    long long total = (long long)nplanes * H_DIM * W4;
    if (tid >= total) return;

    int c4 = (int)(tid % W4);
    long long t2 = tid / W4;
    int r = (int)(t2 % H_DIM);
    int p = (int)(t2 / H_DIM);

    const float* plane = x + (long long)p * H_DIM * W_DIM;
    const float* rowp  = plane + (long long)r * W_DIM;

    // center vector
    float4 v = __ldg((const float4*)rowp + c4);

    // vertical neighbors with replicate clamp
    int rup = r > 0 ? r - 1 : 0;
    int rdn = r < H_DIM - 1 ? r + 1 : H_DIM - 1;
    float4 u = __ldg((const float4*)(plane + (long long)rup * W_DIM) + c4);
    float4 d = __ldg((const float4*)(plane + (long long)rdn * W_DIM) + c4);

    // horizontal halo: shuffle from warp neighbors; edges load/clamp.
    int lane = threadIdx.x & 31;
    int c = c4 << 2;
    float left  = __shfl_up_sync(0xFFFFFFFFu, v.w, 1);
    float right = __shfl_down_sync(0xFFFFFFFFu, v.x, 1);
    if (lane == 0)
        left = (c == 0) ? v.x : __ldg(rowp + c - 1);
    if (lane == 31)
        right = (c + 4 == W_DIM) ? v.w : __ldg(rowp + c + 4);

    float a0 = __ldg(a + 0), a1 = __ldg(a + 1), a2 = __ldg(a + 2);
    float w0 = __ldg(w + 0), w1 = __ldg(w + 1), w2 = __ldg(w + 2), w3 = __ldg(w + 3);

    float4 o;
    {
        float xv = v.x;
        float st = a0 * xv + a1 * (left + v.y) + a2 * (u.x + d.x);
        float pl = fmaf(fmaf(fmaf(w3, xv, w2), xv, w1), xv, w0);
        o.x = st + pl;
    }
    {
        float xv = v.y;
        float st = a0 * xv + a1 * (v.x + v.z) + a2 * (u.y + d.y);
        float pl = fmaf(fmaf(fmaf(w3, xv, w2), xv, w1), xv, w0);
        o.y = st + pl;
    }
    {
        float xv = v.z;
        float st = a0 * xv + a1 * (v.y + v.w) + a2 * (u.z + d.z);
        float pl = fmaf(fmaf(fmaf(w3, xv, w2), xv, w1), xv, w0);
        o.z = st + pl;
    }
    {
        float xv = v.w;
        float st = a0 * xv + a1 * (v.z + right) + a2 * (u.w + d.w);
        float pl = fmaf(fmaf(fmaf(w3, xv, w2), xv, w1), xv, w0);
        o.w = st + pl;
    }

    float4* orow = (float4*)(out + (long long)p * H_DIM * W_DIM + (long long)r * W_DIM);
    orow[c4] = o;
}

extern "C" void kernel_launch(void* const* d_in, const int* in_sizes, int n_in,
                              void* d_out, int out_size)
{
    const float* x = (const float*)d_in[0];
    const float* a = (const float*)d_in[1];
    const float* w = (const float*)d_in[2];
    float* out = (float*)d_out;

    int n = in_sizes[0];
    int nplanes = n / (H_DIM * W_DIM);  // B*C = 16

    long long total4 = (long long)nplanes * H_DIM * (W_DIM / 4);
    int threads = 256;
    long long blocks = (total4 + threads - 1) / threads;

    stencil_poly_vec4<<<(unsigned)blocks, threads>>>(x, a, w, out, nplanes);
}

// round 3
// speedup vs baseline: 1.1000x; 1.0963x over previous
#include <cuda_runtime.h>

// Fused 5-point replicate-pad stencil + cubic Horner polynomial.
// R3: 2 rows per thread — 4 row-loads produce 2 outputs (2 loads/output vs 3),
// cutting L2 read traffic 33% and raising per-thread MLP to 4.

#define H_DIM 2048
#define W_DIM 2048

__global__ void __launch_bounds__(256) stencil_poly_2row(
    const float* __restrict__ x,
    const float* __restrict__ a,
    const float* __restrict__ w,
    float* __restrict__ out,
    int nplanes)
{
    const int W4 = W_DIM >> 2;      // 512
    const int HP = H_DIM >> 1;      // 1024 row-pairs

    long long tid = (long long)blockIdx.x * blockDim.x + threadIdx.x;
    long long total = (long long)nplanes * HP * W4;
    if (tid >= total) return;

    int c4 = (int)(tid % W4);
    long long t2 = tid / W4;
    int rp = (int)(t2 % HP);
    int p  = (int)(t2 / HP);

    int r0 = rp << 1;           // even row
    int r1 = r0 + 1;            // odd row

    const float* plane = x + (long long)p * H_DIM * W_DIM;

    // four row loads with replicate clamp at top/bottom
    int rm = (r0 > 0) ? r0 - 1 : 0;
    int rb = (r1 < H_DIM - 1) ? r1 + 1 : H_DIM - 1;

    float4 vu = __ldg((const float4*)(plane + (long long)rm * W_DIM) + c4);
    float4 v0 = __ldg((const float4*)(plane + (long long)r0 * W_DIM) + c4);
    float4 v1 = __ldg((const float4*)(plane + (long long)r1 * W_DIM) + c4);
    float4 vd = __ldg((const float4*)(plane + (long long)rb * W_DIM) + c4);

    // horizontal halo via shuffle (warps are row-aligned: 512 % 32 == 0)
    int lane = threadIdx.x & 31;
    int c = c4 << 2;
    float l0 = __shfl_up_sync(0xFFFFFFFFu, v0.w, 1);
    float r0h = __shfl_down_sync(0xFFFFFFFFu, v0.x, 1);
    float l1 = __shfl_up_sync(0xFFFFFFFFu, v1.w, 1);
    float r1h = __shfl_down_sync(0xFFFFFFFFu, v1.x, 1);
    if (lane == 0) {
        const float* row0 = plane + (long long)r0 * W_DIM;
        const float* row1 = plane + (long long)r1 * W_DIM;
        l0 = (c == 0) ? v0.x : __ldg(row0 + c - 1);
        l1 = (c == 0) ? v1.x : __ldg(row1 + c - 1);
    }
    if (lane == 31) {
        const float* row0 = plane + (long long)r0 * W_DIM;
        const float* row1 = plane + (long long)r1 * W_DIM;
        r0h = (c + 4 == W_DIM) ? v0.w : __ldg(row0 + c + 4);
        r1h = (c + 4 == W_DIM) ? v1.w : __ldg(row1 + c + 4);
    }

    float a0 = __ldg(a + 0), a1 = __ldg(a + 1), a2 = __ldg(a + 2);
    float w0 = __ldg(w + 0), w1 = __ldg(w + 1), w2 = __ldg(w + 2), w3 = __ldg(w + 3);

    // row r0: up = vu, down = v1
    float4 o0;
    {
        float xv = v0.x;
        o0.x = a0*xv + a1*(l0   + v0.y) + a2*(vu.x + v1.x)
             + fmaf(fmaf(fmaf(w3, xv, w2), xv, w1), xv, w0);
        xv = v0.y;
        o0.y = a0*xv + a1*(v0.x + v0.z) + a2*(vu.y + v1.y)
             + fmaf(fmaf(fmaf(w3, xv, w2), xv, w1), xv, w0);
        xv = v0.z;
        o0.z = a0*xv + a1*(v0.y + v0.w) + a2*(vu.z + v1.z)
             + fmaf(fmaf(fmaf(w3, xv, w2), xv, w1), xv, w0);
        xv = v0.w;
        o0.w = a0*xv + a1*(v0.z + r0h ) + a2*(vu.w + v1.w)
             + fmaf(fmaf(fmaf(w3, xv, w2), xv, w1), xv, w0);
    }
    // row r1: up = v0, down = vd
    float4 o1;
    {
        float xv = v1.x;
        o1.x = a0*xv + a1*(l1   + v1.y) + a2*(v0.x + vd.x)
             + fmaf(fmaf(fmaf(w3, xv, w2), xv, w1), xv, w0);
        xv = v1.y;
        o1.y = a0*xv + a1*(v1.x + v1.z) + a2*(v0.y + vd.y)
             + fmaf(fmaf(fmaf(w3, xv, w2), xv, w1), xv, w0);
        xv = v1.z;
        o1.z = a0*xv + a1*(v1.y + v1.w) + a2*(v0.z + vd.z)
             + fmaf(fmaf(fmaf(w3, xv, w2), xv, w1), xv, w0);
        xv = v1.w;
        o1.w = a0*xv + a1*(v1.z + r1h ) + a2*(v0.w + vd.w)
             + fmaf(fmaf(fmaf(w3, xv, w2), xv, w1), xv, w0);
    }

    float* oplane = out + (long long)p * H_DIM * W_DIM;
    ((float4*)(oplane + (long long)r0 * W_DIM))[c4] = o0;
    ((float4*)(oplane + (long long)r1 * W_DIM))[c4] = o1;
}

extern "C" void kernel_launch(void* const* d_in, const int* in_sizes, int n_in,
                              void* d_out, int out_size)
{
    const float* x = (const float*)d_in[0];
    const float* a = (const float*)d_in[1];
    const float* w = (const float*)d_in[2];
    float* out = (float*)d_out;

    int n = in_sizes[0];
    int nplanes = n / (H_DIM * W_DIM);  // B*C = 16

    long long total = (long long)nplanes * (H_DIM / 2) * (W_DIM / 4);
    int threads = 256;
    long long blocks = (total + threads - 1) / threads;

    stencil_poly_2row<<<(unsigned)blocks, threads>>>(x, a, w, out, nplanes);
}

// round 4
// speedup vs baseline: 1.1756x; 1.0687x over previous
#include <cuda_runtime.h>

// Fused 5-point replicate-pad stencil + cubic Horner polynomial.
// R4: 4 rows per thread — 6 row-loads produce 4 outputs (1.5 loads/output),
// MLP_p1=6 front-batched LDG.128, streaming stores (__stcs).

#define H_DIM 2048
#define W_DIM 2048

__global__ void __launch_bounds__(256) stencil_poly_4row(
    const float* __restrict__ x,
    const float* __restrict__ a,
    const float* __restrict__ w,
    float* __restrict__ out,
    int nplanes)
{
    const int W4 = W_DIM >> 2;      // 512
    const int HQ = H_DIM >> 2;      // 512 row-quads

    long long tid = (long long)blockIdx.x * blockDim.x + threadIdx.x;
    long long total = (long long)nplanes * HQ * W4;
    if (tid >= total) return;

    int c4 = (int)(tid % W4);
    long long t2 = tid / W4;
    int rq = (int)(t2 % HQ);
    int p  = (int)(t2 / HQ);

    int rbase = rq << 2;            // first of 4 rows

    const float* plane = x + (long long)p * H_DIM * W_DIM;

    // 6 row loads: rbase-1 .. rbase+4, clamped at plane edges.
    int rtop = (rbase > 0) ? rbase - 1 : 0;
    int rbot = (rbase + 4 < H_DIM) ? rbase + 4 : H_DIM - 1;

    float4 v[6];
    v[0] = __ldg((const float4*)(plane + (long long)rtop       * W_DIM) + c4);
    v[1] = __ldg((const float4*)(plane + (long long)(rbase    ) * W_DIM) + c4);
    v[2] = __ldg((const float4*)(plane + (long long)(rbase + 1) * W_DIM) + c4);
    v[3] = __ldg((const float4*)(plane + (long long)(rbase + 2) * W_DIM) + c4);
    v[4] = __ldg((const float4*)(plane + (long long)(rbase + 3) * W_DIM) + c4);
    v[5] = __ldg((const float4*)(plane + (long long)rbot        * W_DIM) + c4);

    // horizontal halo via shuffle for the 4 center rows (warps row-aligned).
    int lane = threadIdx.x & 31;
    int c = c4 << 2;
    float lh[4], rh[4];
    #pragma unroll
    for (int i = 0; i < 4; i++) {
        lh[i] = __shfl_up_sync  (0xFFFFFFFFu, v[i + 1].w, 1);
        rh[i] = __shfl_down_sync(0xFFFFFFFFu, v[i + 1].x, 1);
    }
    if (lane == 0) {
        #pragma unroll
        for (int i = 0; i < 4; i++) {
            const float* row = plane + (long long)(rbase + i) * W_DIM;
            lh[i] = (c == 0) ? v[i + 1].x : __ldg(row + c - 1);
        }
    }
    if (lane == 31) {
        #pragma unroll
        for (int i = 0; i < 4; i++) {
            const float* row = plane + (long long)(rbase + i) * W_DIM;
            rh[i] = (c + 4 == W_DIM) ? v[i + 1].w : __ldg(row + c + 4);
        }
    }

    float a0 = __ldg(a + 0), a1 = __ldg(a + 1), a2 = __ldg(a + 2);
    float w0 = __ldg(w + 0), w1 = __ldg(w + 1), w2 = __ldg(w + 2), w3 = __ldg(w + 3);

    float* oplane = out + (long long)p * H_DIM * W_DIM;

    #pragma unroll
    for (int i = 0; i < 4; i++) {
        float4 cv = v[i + 1];
        float4 up = v[i];
        float4 dn = v[i + 2];
        float4 o;

        float xv = cv.x;
        o.x = a0*xv + a1*(lh[i] + cv.y) + a2*(up.x + dn.x)
            + fmaf(fmaf(fmaf(w3, xv, w2), xv, w1), xv, w0);
        xv = cv.y;
        o.y = a0*xv + a1*(cv.x + cv.z) + a2*(up.y + dn.y)
            + fmaf(fmaf(fmaf(w3, xv, w2), xv, w1), xv, w0);
        xv = cv.z;
        o.z = a0*xv + a1*(cv.y + cv.w) + a2*(up.z + dn.z)
            + fmaf(fmaf(fmaf(w3, xv, w2), xv, w1), xv, w0);
        xv = cv.w;
        o.w = a0*xv + a1*(cv.z + rh[i]) + a2*(up.w + dn.w)
            + fmaf(fmaf(fmaf(w3, xv, w2), xv, w1), xv, w0);

        __stcs((float4*)(oplane + (long long)(rbase + i) * W_DIM) + c4, o);
    }
}

extern "C" void kernel_launch(void* const* d_in, const int* in_sizes, int n_in,
                              void* d_out, int out_size)
{
    const float* x = (const float*)d_in[0];
    const float* a = (const float*)d_in[1];
    const float* w = (const float*)d_in[2];
    float* out = (float*)d_out;

    int n = in_sizes[0];
    int nplanes = n / (H_DIM * W_DIM);  // B*C = 16

    long long total = (long long)nplanes * (H_DIM / 4) * (W_DIM / 4);
    int threads = 256;
    long long blocks = (total + threads - 1) / threads;

    stencil_poly_4row<<<(unsigned)blocks, threads>>>(x, a, w, out, nplanes);
}